// round 11
// baseline (speedup 1.0000x reference)
#include <cuda_runtime.h>

#define N_NODES 768
#define INP     256
#define H       4
#define FH      64
#define OUTD    256   // H*FH
#define NSPLIT  4
#define JSPAN   (N_NODES / NSPLIT)   // 192
#define TI      16
#define TJ      64
#define WXJ_PAD 70
#define NIBLK   (N_NODES / TI)       // 48

typedef unsigned long long u64;

// Scratch (no cudaMalloc allowed)
__device__ float g_Wx[N_NODES * OUTD];
__device__ float g_E[N_NODES * H];
__device__ float g_pm[N_NODES * H][NSPLIT];
__device__ float g_ps[N_NODES * H][NSPLIT];
__device__ float g_pacc[N_NODES * H][NSPLIT][FH];
__device__ int   g_cnt[NIBLK * H];   // zero-init; reset by last block each launch

// ---------------- packed f32x2 helpers (sm_103a) ----------------
__device__ __forceinline__ u64 pk2(float x, float y) {
    u64 r; asm("mov.b64 %0,{%1,%2};" : "=l"(r) : "f"(x), "f"(y)); return r;
}
__device__ __forceinline__ float2 upk2(u64 v) {
    float2 r; asm("mov.b64 {%0,%1},%2;" : "=f"(r.x), "=f"(r.y) : "l"(v)); return r;
}
__device__ __forceinline__ void mac_abs2(u64& acc, u64 av, u64 wi, u64 sj) {
    u64 t;
    asm("add.rn.f32x2 %0,%1,%2;" : "=l"(t) : "l"(wi), "l"(sj));
    asm("and.b64 %0,%0,0x7FFFFFFF7FFFFFFF;" : "+l"(t));
    asm("fma.rn.f32x2 %0,%1,%2,%0;" : "+l"(acc) : "l"(av), "l"(t));
}
__device__ __forceinline__ void fma2(u64& acc, u64 a, u64 b) {
    asm("fma.rn.f32x2 %0,%1,%2,%0;" : "+l"(acc) : "l"(a), "l"(b));
}
__device__ __forceinline__ void mul2(u64& acc, u64 a) {
    asm("mul.rn.f32x2 %0,%0,%1;" : "+l"(acc) : "l"(a));
}
// LDS.128 into two u64 (one broadcast feeds two packed operands)
__device__ __forceinline__ void lds_v2u64(u64& a, u64& b, const void* p) {
    unsigned s = (unsigned)__cvta_generic_to_shared(p);
    asm("ld.shared.v2.u64 {%0,%1}, [%2];" : "=l"(a), "=l"(b) : "r"(s));
}

// ---------------------------------------------------------------------------
// GEMM: Wx = x @ W^T.  Whole-K staging: x-tile (32x256) + W-head (64x256) in
// 102 KB dynamic smem, ONE barrier, then 256 uninterrupted k-iterations.
// 256 threads, 2x4 per-thread tile. Grid (H, 24) = 96 blocks. Fused E epilogue.
// ---------------------------------------------------------------------------
#define AS_PAD 34    // [k][m] rows of 34 floats (8B-aligned for LDS.64)
#define BS_PAD 68    // [k][n] rows of 68 floats (16B-aligned for LDS.128)
#define GEMM_SMEM ((INP * AS_PAD + INP * BS_PAD) * 4)   // 104448 B

__global__ __launch_bounds__(256) void gemm_kernel(const float* __restrict__ x,
                                                   const float* __restrict__ W,
                                                   const float* __restrict__ a) {
    extern __shared__ float smem[];
    float (*As)[AS_PAD] = reinterpret_cast<float (*)[AS_PAD]>(smem);
    float (*Bs)[BS_PAD] = reinterpret_cast<float (*)[BS_PAD]>(smem + INP * AS_PAD);

    const int tid = threadIdx.x;
    const int h   = blockIdx.x;
    const int m0  = blockIdx.y * 32;
    const int n0  = h * 64;

    // ---- stage x: 32 rows x 64 k-float4 = 2048 float4, 8 per thread ----
    #pragma unroll
    for (int c = 0; c < 8; c++) {
        const int id = tid + c * 256;
        const int m = id / 64, k4 = id % 64;
        float4 v = *reinterpret_cast<const float4*>(&x[(m0 + m) * INP + k4 * 4]);
        As[k4 * 4 + 0][m] = v.x; As[k4 * 4 + 1][m] = v.y;
        As[k4 * 4 + 2][m] = v.z; As[k4 * 4 + 3][m] = v.w;
    }
    // ---- stage W: 64 rows x 64 k-float4 = 4096 float4, 16 per thread ----
    #pragma unroll
    for (int c = 0; c < 16; c++) {
        const int id = tid + c * 256;
        const int n = id / 64, k4 = id % 64;
        float4 v = *reinterpret_cast<const float4*>(&W[(n0 + n) * INP + k4 * 4]);
        Bs[k4 * 4 + 0][n] = v.x; Bs[k4 * 4 + 1][n] = v.y;
        Bs[k4 * 4 + 2][n] = v.z; Bs[k4 * 4 + 3][n] = v.w;
    }
    __syncthreads();

    const int tx = tid % 16;   // n quad
    const int ty = tid / 16;   // m pair
    float acc[2][4] = {};
    #pragma unroll 8
    for (int k = 0; k < INP; k++) {
        float2 av = *reinterpret_cast<const float2*>(&As[k][ty * 2]);
        float4 bv = *reinterpret_cast<const float4*>(&Bs[k][tx * 4]);
        acc[0][0] += av.x * bv.x; acc[0][1] += av.x * bv.y;
        acc[0][2] += av.x * bv.z; acc[0][3] += av.x * bv.w;
        acc[1][0] += av.y * bv.x; acc[1][1] += av.y * bv.y;
        acc[1][2] += av.y * bv.z; acc[1][3] += av.y * bv.w;
    }

    float4 a4v = *reinterpret_cast<const float4*>(&a[tx * 4]);
    #pragma unroll
    for (int u = 0; u < 2; u++) {
        const int m = m0 + ty * 2 + u;
        *reinterpret_cast<float4*>(&g_Wx[m * OUTD + n0 + tx * 4]) =
            make_float4(acc[u][0], acc[u][1], acc[u][2], acc[u][3]);
        float ev = a4v.x * acc[u][0] + a4v.y * acc[u][1]
                 + a4v.z * acc[u][2] + a4v.w * acc[u][3];
        #pragma unroll
        for (int off = 1; off < 16; off <<= 1)
            ev += __shfl_xor_sync(0xffffffffu, ev, off);
        if (tx == 0) g_E[m * H + h] = ev;
    }
}

// ---------------------------------------------------------------------------
// Split-KV flash attention (proven mainloop) + fused split-combine epilogue.
// Block = (16 i-rows, head, j-split of 192). 128 threads, warp w owns rows
// {w, w+4, w+8, w+12}. Last-arriving split block merges partials -> out.
// ---------------------------------------------------------------------------
__global__ __launch_bounds__(128) void attn_kernel(const int* __restrict__ adj,
                                                   const float* __restrict__ a,
                                                   float* __restrict__ out) {
    __shared__ __align__(16) float wxj[TJ][WXJ_PAD];   // 17.9 KB
    __shared__ float4 wi4[2][4][32];                   // 4 KB
    __shared__ float4 p_ab[4][TJ];                     // 4 KB
    __shared__ float4 p_cd[4][TJ];                     // 4 KB
    __shared__ u64    av2[FH / 2];
    __shared__ float  e06s[JSPAN];
    __shared__ int    is_last;

    const int tid  = threadIdx.x;
    const int w    = tid / 32;
    const int lane = tid % 32;
    const int h    = blockIdx.y;
    const int iblk = blockIdx.x >> 2;
    const int sp   = blockIdx.x & 3;
    const int i0   = iblk * TI;
    const int jbase = sp * JSPAN;

    // ---- stage per-block constants ----
    for (int id = tid; id < 256; id += 128) {
        const int q = id >> 7, rem = id & 127;
        const int w2 = rem >> 5, k = rem & 31;
        const int r0 = w2 + 8 * q, r1 = r0 + 4;
        float2 lo = *reinterpret_cast<const float2*>(&g_Wx[(i0 + r0) * OUTD + h * FH + 2 * k]);
        float2 hi = *reinterpret_cast<const float2*>(&g_Wx[(i0 + r1) * OUTD + h * FH + 2 * k]);
        wi4[q][w2][k] = make_float4(lo.x, lo.y, hi.x, hi.y);
    }
    if (tid < FH / 2)
        av2[tid] = *reinterpret_cast<const u64*>(&a[2 * tid]);
    for (int id = tid; id < JSPAN; id += 128)
        e06s[id] = 0.6f * g_E[(jbase + id) * H + h];

    const int rA = i0 + w, rB = rA + 4, rC = rA + 8, rD = rA + 12;
    const float eiA = 0.6f * g_E[rA * H + h];
    const float eiB = 0.6f * g_E[rB * H + h];
    const float eiC = 0.6f * g_E[rC * H + h];
    const float eiD = 0.6f * g_E[rD * H + h];
    const int* adjA = &adj[rA * N_NODES + jbase];
    const int* adjB = &adj[rB * N_NODES + jbase];
    const int* adjC = &adj[rC * N_NODES + jbase];
    const int* adjD = &adj[rD * N_NODES + jbase];

    float mA = -1e30f, sA = 0.f, mB = -1e30f, sB = 0.f;
    float mC = -1e30f, sC = 0.f, mD = -1e30f, sD = 0.f;
    u64 accA = 0, accB = 0, accC = 0, accD = 0;

    for (int jt = 0; jt < JSPAN; jt += TJ) {
        __syncthreads();
        // ---- stage wxj tile (64 rows x 64 f): 1024 float4, 8/thread ----
        #pragma unroll
        for (int r = 0; r < 8; r++) {
            const int id = tid + r * 128;
            const int jj = id / 16, c4 = id % 16;
            float4 v = *reinterpret_cast<const float4*>(
                &g_Wx[(jbase + jt + jj) * OUTD + h * FH + c4 * 4]);
            *reinterpret_cast<float2*>(&wxj[jj][c4 * 4])     = make_float2(v.x, v.y);
            *reinterpret_cast<float2*>(&wxj[jj][c4 * 4 + 2]) = make_float2(v.z, v.w);
        }
        __syncthreads();

        // ---- e-phase: lane j-cols (jt+lane, jt+32+lane) x 4 rows ----
        const u64* wj0 = reinterpret_cast<const u64*>(&wxj[lane][0]);
        const u64* wj1 = reinterpret_cast<const u64*>(&wxj[lane + 32][0]);
        u64 eA0 = 0, eA1 = 0, eB0 = 0, eB1 = 0;
        u64 eC0 = 0, eC1 = 0, eD0 = 0, eD1 = 0;
        #pragma unroll
        for (int k = 0; k < 32; k++) {
            const u64 avk = av2[k];
            u64 wa, wb, wc, wd;
            lds_v2u64(wa, wb, &wi4[0][w][k]);
            lds_v2u64(wc, wd, &wi4[1][w][k]);
            const u64 j0 = wj0[k];
            const u64 j1 = wj1[k];
            mac_abs2(eA0, avk, wa, j0);  mac_abs2(eA1, avk, wa, j1);
            mac_abs2(eB0, avk, wb, j0);  mac_abs2(eB1, avk, wb, j1);
            mac_abs2(eC0, avk, wc, j0);  mac_abs2(eC1, avk, wc, j1);
            mac_abs2(eD0, avk, wd, j0);  mac_abs2(eD1, avk, wd, j1);
        }
        const float ej0 = e06s[jt + lane], ej1 = e06s[jt + 32 + lane];
        float2 f;
        f = upk2(eA0); float e_A0 = eiA + ej0 + 0.4f * (f.x + f.y);
        f = upk2(eA1); float e_A1 = eiA + ej1 + 0.4f * (f.x + f.y);
        f = upk2(eB0); float e_B0 = eiB + ej0 + 0.4f * (f.x + f.y);
        f = upk2(eB1); float e_B1 = eiB + ej1 + 0.4f * (f.x + f.y);
        f = upk2(eC0); float e_C0 = eiC + ej0 + 0.4f * (f.x + f.y);
        f = upk2(eC1); float e_C1 = eiC + ej1 + 0.4f * (f.x + f.y);
        f = upk2(eD0); float e_D0 = eiD + ej0 + 0.4f * (f.x + f.y);
        f = upk2(eD1); float e_D1 = eiD + ej1 + 0.4f * (f.x + f.y);
        if (adjA[jt + lane]      == 0) e_A0 = -1e30f;
        if (adjA[jt + 32 + lane] == 0) e_A1 = -1e30f;
        if (adjB[jt + lane]      == 0) e_B0 = -1e30f;
        if (adjB[jt + 32 + lane] == 0) e_B1 = -1e30f;
        if (adjC[jt + lane]      == 0) e_C0 = -1e30f;
        if (adjC[jt + 32 + lane] == 0) e_C1 = -1e30f;
        if (adjD[jt + lane]      == 0) e_D0 = -1e30f;
        if (adjD[jt + 32 + lane] == 0) e_D1 = -1e30f;

        // ---- online softmax update, 4 rows ----
        float tA = fmaxf(e_A0, e_A1), tB = fmaxf(e_B0, e_B1);
        float tC = fmaxf(e_C0, e_C1), tD = fmaxf(e_D0, e_D1);
        #pragma unroll
        for (int off = 16; off > 0; off >>= 1) {
            tA = fmaxf(tA, __shfl_xor_sync(0xffffffffu, tA, off));
            tB = fmaxf(tB, __shfl_xor_sync(0xffffffffu, tB, off));
            tC = fmaxf(tC, __shfl_xor_sync(0xffffffffu, tC, off));
            tD = fmaxf(tD, __shfl_xor_sync(0xffffffffu, tD, off));
        }
        const float nA = fmaxf(mA, tA), nB = fmaxf(mB, tB);
        const float nC = fmaxf(mC, tC), nD = fmaxf(mD, tD);
        const float scA = __expf(mA - nA), scB = __expf(mB - nB);
        const float scC = __expf(mC - nC), scD = __expf(mD - nD);
        const float pA0 = __expf(e_A0 - nA), pA1 = __expf(e_A1 - nA);
        const float pB0 = __expf(e_B0 - nB), pB1 = __expf(e_B1 - nB);
        const float pC0 = __expf(e_C0 - nC), pC1 = __expf(e_C1 - nC);
        const float pD0 = __expf(e_D0 - nD), pD1 = __expf(e_D1 - nD);
        sA = sA * scA + pA0 + pA1;  sB = sB * scB + pB0 + pB1;
        sC = sC * scC + pC0 + pC1;  sD = sD * scD + pD0 + pD1;
        mul2(accA, pk2(scA, scA));  mul2(accB, pk2(scB, scB));
        mul2(accC, pk2(scC, scC));  mul2(accD, pk2(scD, scD));
        mA = nA; mB = nB; mC = nC; mD = nD;

        p_ab[w][lane]      = make_float4(pA0, pA0, pB0, pB0);
        p_ab[w][lane + 32] = make_float4(pA1, pA1, pB1, pB1);
        p_cd[w][lane]      = make_float4(pC0, pC0, pD0, pD0);
        p_cd[w][lane + 32] = make_float4(pC1, pC1, pD1, pD1);
        __syncwarp();

        // ---- aggregation: one wv read feeds 4 rows ----
        #pragma unroll
        for (int jj = 0; jj < TJ; jj++) {
            const u64 wv = *reinterpret_cast<const u64*>(&wxj[jj][lane * 2]);
            u64 pa2, pb2, pc2, pd2;
            lds_v2u64(pa2, pb2, &p_ab[w][jj]);
            lds_v2u64(pc2, pd2, &p_cd[w][jj]);
            fma2(accA, pa2, wv);
            fma2(accB, pb2, wv);
            fma2(accC, pc2, wv);
            fma2(accD, pd2, wv);
        }
        __syncwarp();   // agg done before next tile's p overwrite
    }

    // ---- reduce per-lane s partials across the warp ----
    #pragma unroll
    for (int off = 16; off > 0; off >>= 1) {
        sA += __shfl_xor_sync(0xffffffffu, sA, off);
        sB += __shfl_xor_sync(0xffffffffu, sB, off);
        sC += __shfl_xor_sync(0xffffffffu, sC, off);
        sD += __shfl_xor_sync(0xffffffffu, sD, off);
    }

    // ---- write partials (unnormalized) ----
    const int gA = rA * H + h, gB = rB * H + h, gC = rC * H + h, gD = rD * H + h;
    if (lane == 0) {
        g_pm[gA][sp] = mA; g_ps[gA][sp] = sA;
        g_pm[gB][sp] = mB; g_ps[gB][sp] = sB;
        g_pm[gC][sp] = mC; g_ps[gC][sp] = sC;
        g_pm[gD][sp] = mD; g_ps[gD][sp] = sD;
    }
    float2 o;
    o = upk2(accA); *reinterpret_cast<float2*>(&g_pacc[gA][sp][2 * lane]) = o;
    o = upk2(accB); *reinterpret_cast<float2*>(&g_pacc[gB][sp][2 * lane]) = o;
    o = upk2(accC); *reinterpret_cast<float2*>(&g_pacc[gC][sp][2 * lane]) = o;
    o = upk2(accD); *reinterpret_cast<float2*>(&g_pacc[gD][sp][2 * lane]) = o;

    // ---- fused combine: last split block for (iblk, h) merges all partials ----
    __threadfence();
    __syncthreads();
    if (tid == 0) {
        int old = atomicAdd(&g_cnt[iblk * H + h], 1);
        is_last = (old == NSPLIT - 1) ? 1 : 0;
    }
    __syncthreads();
    if (is_last) {
        __threadfence();   // acquire: other blocks' fenced writes now visible
        #pragma unroll
        for (int r = 0; r < 4; r++) {
            const int row = i0 + w * 4 + r;
            const int g = row * H + h;
            float mp = (lane < NSPLIT) ? g_pm[g][lane] : -1e30f;
            float ms = mp;
            #pragma unroll
            for (int off = 16; off > 0; off >>= 1)
                ms = fmaxf(ms, __shfl_xor_sync(0xffffffffu, ms, off));
            float fac = (lane < NSPLIT) ? __expf(mp - ms) : 0.f;
            float sv  = (lane < NSPLIT) ? g_ps[g][lane] * fac : 0.f;
            #pragma unroll
            for (int off = 16; off > 0; off >>= 1)
                sv += __shfl_xor_sync(0xffffffffu, sv, off);
            const float f0 = __shfl_sync(0xffffffffu, fac, 0);
            const float f1 = __shfl_sync(0xffffffffu, fac, 1);
            const float f2 = __shfl_sync(0xffffffffu, fac, 2);
            const float f3 = __shfl_sync(0xffffffffu, fac, 3);
            float2 a0 = *reinterpret_cast<const float2*>(&g_pacc[g][0][2 * lane]);
            float2 a1 = *reinterpret_cast<const float2*>(&g_pacc[g][1][2 * lane]);
            float2 a2 = *reinterpret_cast<const float2*>(&g_pacc[g][2][2 * lane]);
            float2 a3 = *reinterpret_cast<const float2*>(&g_pacc[g][3][2 * lane]);
            const float inv = 1.f / sv;
            float ox = (a0.x * f0 + a1.x * f1 + a2.x * f2 + a3.x * f3) * inv;
            float oy = (a0.y * f0 + a1.y * f1 + a2.y * f2 + a3.y * f3) * inv;
            *reinterpret_cast<float2*>(&out[row * OUTD + h * FH + 2 * lane]) =
                make_float2(ox, oy);
        }
        __syncthreads();
        if (tid == 0) g_cnt[iblk * H + h] = 0;   // reset for next launch (deterministic)
    }
}

// ---------------------------------------------------------------------------
extern "C" void kernel_launch(void* const* d_in, const int* in_sizes, int n_in,
                              void* d_out, int out_size) {
    const float* x = nullptr;
    const int*   adj = nullptr;
    const float* W = nullptr;
    const float* a = nullptr;
    for (int i = 0; i < n_in; i++) {
        switch (in_sizes[i]) {
            case N_NODES * INP:      x   = (const float*)d_in[i]; break;
            case N_NODES * N_NODES:  adj = (const int*)d_in[i];   break;
            case OUTD * INP:         W   = (const float*)d_in[i]; break;
            case FH:                 a   = (const float*)d_in[i]; break;
            default: break;
        }
    }
    float* out = (float*)d_out;

    // >48KB dynamic smem opt-in (host state call; idempotent; not an allocation)
    cudaFuncSetAttribute(gemm_kernel,
                         cudaFuncAttributeMaxDynamicSharedMemorySize, GEMM_SMEM);

    dim3 gg(H, N_NODES / 32);                     // 4 x 24 = 96 blocks
    gemm_kernel<<<gg, 256, GEMM_SMEM>>>(x, W, a);
    dim3 ga((N_NODES / TI) * NSPLIT, H);          // 192 x 4 = 768 blocks
    attn_kernel<<<ga, 128>>>(adj, a, out);
}

// round 12
// speedup vs baseline: 1.0429x; 1.0429x over previous
#include <cuda_runtime.h>

#define N_NODES 768
#define INP     256
#define H       4
#define FH      64
#define OUTD    256   // H*FH
#define NSPLIT  4
#define JSPAN   (N_NODES / NSPLIT)   // 192
#define TI      16
#define TJ      64
#define WXJ_PAD 70

typedef unsigned long long u64;

// Scratch (no cudaMalloc allowed)
__device__ float g_Wx[N_NODES * OUTD];
__device__ float g_E[N_NODES * H];
__device__ float g_pm[N_NODES * H][NSPLIT];
__device__ float g_ps[N_NODES * H][NSPLIT];
__device__ float g_pacc[N_NODES * H][NSPLIT][FH];

// ---------------- packed f32x2 helpers (sm_103a) ----------------
__device__ __forceinline__ u64 pk2(float x, float y) {
    u64 r; asm("mov.b64 %0,{%1,%2};" : "=l"(r) : "f"(x), "f"(y)); return r;
}
__device__ __forceinline__ float2 upk2(u64 v) {
    float2 r; asm("mov.b64 {%0,%1},%2;" : "=f"(r.x), "=f"(r.y) : "l"(v)); return r;
}
__device__ __forceinline__ void mac_abs2(u64& acc, u64 av, u64 wi, u64 sj) {
    u64 t;
    asm("add.rn.f32x2 %0,%1,%2;" : "=l"(t) : "l"(wi), "l"(sj));
    asm("and.b64 %0,%0,0x7FFFFFFF7FFFFFFF;" : "+l"(t));
    asm("fma.rn.f32x2 %0,%1,%2,%0;" : "+l"(acc) : "l"(av), "l"(t));
}
__device__ __forceinline__ void fma2(u64& acc, u64 a, u64 b) {
    asm("fma.rn.f32x2 %0,%1,%2,%0;" : "+l"(acc) : "l"(a), "l"(b));
}
__device__ __forceinline__ void mul2(u64& acc, u64 a) {
    asm("mul.rn.f32x2 %0,%0,%1;" : "+l"(acc) : "l"(a));
}
// LDS.128 into two u64 (one broadcast feeds two packed operands)
__device__ __forceinline__ void lds_v2u64(u64& a, u64& b, const void* p) {
    unsigned s = (unsigned)__cvta_generic_to_shared(p);
    asm("ld.shared.v2.u64 {%0,%1}, [%2];" : "=l"(a), "=l"(b) : "r"(s));
}

// ---------------------------------------------------------------------------
// GEMM: Wx = x @ W^T.  Whole-K staging: x-tile (32x256) + W-head (64x256) in
// 102 KB dynamic smem, ONE barrier, then 256 uninterrupted k-iterations.
// 256 threads, 2x4 per-thread tile. Grid (H, 24) = 96 blocks. Fused E epilogue.
// (Round-11 proven body, unchanged: 14.6 -> ~11.5 us.)
// ---------------------------------------------------------------------------
#define AS_PAD 34
#define BS_PAD 68
#define GEMM_SMEM ((INP * AS_PAD + INP * BS_PAD) * 4)   // 104448 B

__global__ __launch_bounds__(256) void gemm_kernel(const float* __restrict__ x,
                                                   const float* __restrict__ W,
                                                   const float* __restrict__ a) {
    extern __shared__ float smem[];
    float (*As)[AS_PAD] = reinterpret_cast<float (*)[AS_PAD]>(smem);
    float (*Bs)[BS_PAD] = reinterpret_cast<float (*)[BS_PAD]>(smem + INP * AS_PAD);

    const int tid = threadIdx.x;
    const int h   = blockIdx.x;
    const int m0  = blockIdx.y * 32;
    const int n0  = h * 64;

    // ---- stage x: 32 rows x 64 k-float4 = 2048 float4, 8 per thread ----
    #pragma unroll
    for (int c = 0; c < 8; c++) {
        const int id = tid + c * 256;
        const int m = id / 64, k4 = id % 64;
        float4 v = *reinterpret_cast<const float4*>(&x[(m0 + m) * INP + k4 * 4]);
        As[k4 * 4 + 0][m] = v.x; As[k4 * 4 + 1][m] = v.y;
        As[k4 * 4 + 2][m] = v.z; As[k4 * 4 + 3][m] = v.w;
    }
    // ---- stage W: 64 rows x 64 k-float4 = 4096 float4, 16 per thread ----
    #pragma unroll
    for (int c = 0; c < 16; c++) {
        const int id = tid + c * 256;
        const int n = id / 64, k4 = id % 64;
        float4 v = *reinterpret_cast<const float4*>(&W[(n0 + n) * INP + k4 * 4]);
        Bs[k4 * 4 + 0][n] = v.x; Bs[k4 * 4 + 1][n] = v.y;
        Bs[k4 * 4 + 2][n] = v.z; Bs[k4 * 4 + 3][n] = v.w;
    }
    __syncthreads();

    const int tx = tid % 16;   // n quad
    const int ty = tid / 16;   // m pair
    float acc[2][4] = {};
    #pragma unroll 8
    for (int k = 0; k < INP; k++) {
        float2 av = *reinterpret_cast<const float2*>(&As[k][ty * 2]);
        float4 bv = *reinterpret_cast<const float4*>(&Bs[k][tx * 4]);
        acc[0][0] += av.x * bv.x; acc[0][1] += av.x * bv.y;
        acc[0][2] += av.x * bv.z; acc[0][3] += av.x * bv.w;
        acc[1][0] += av.y * bv.x; acc[1][1] += av.y * bv.y;
        acc[1][2] += av.y * bv.z; acc[1][3] += av.y * bv.w;
    }

    float4 a4v = *reinterpret_cast<const float4*>(&a[tx * 4]);
    #pragma unroll
    for (int u = 0; u < 2; u++) {
        const int m = m0 + ty * 2 + u;
        *reinterpret_cast<float4*>(&g_Wx[m * OUTD + n0 + tx * 4]) =
            make_float4(acc[u][0], acc[u][1], acc[u][2], acc[u][3]);
        float ev = a4v.x * acc[u][0] + a4v.y * acc[u][1]
                 + a4v.z * acc[u][2] + a4v.w * acc[u][3];
        #pragma unroll
        for (int off = 1; off < 16; off <<= 1)
            ev += __shfl_xor_sync(0xffffffffu, ev, off);
        if (tx == 0) g_E[m * H + h] = ev;
    }
}

// ---------------------------------------------------------------------------
// Split-KV flash attention (round-9 proven body, verbatim — no fused combine).
// Block = (16 i-rows, head, j-split of 192). 128 threads, warp w owns rows
// {w, w+4, w+8, w+12}. Partial (m,s,acc) out.
// ---------------------------------------------------------------------------
__global__ __launch_bounds__(128) void attn_kernel(const int* __restrict__ adj,
                                                   const float* __restrict__ a) {
    __shared__ __align__(16) float wxj[TJ][WXJ_PAD];   // 17.9 KB
    __shared__ float4 wi4[2][4][32];                   // 4 KB
    __shared__ float4 p_ab[4][TJ];                     // 4 KB
    __shared__ float4 p_cd[4][TJ];                     // 4 KB
    __shared__ u64    av2[FH / 2];
    __shared__ float  e06s[JSPAN];

    const int tid  = threadIdx.x;
    const int w    = tid / 32;
    const int lane = tid % 32;
    const int h    = blockIdx.y;
    const int iblk = blockIdx.x >> 2;
    const int sp   = blockIdx.x & 3;
    const int i0   = iblk * TI;
    const int jbase = sp * JSPAN;

    // ---- stage per-block constants ----
    for (int id = tid; id < 256; id += 128) {
        const int q = id >> 7, rem = id & 127;
        const int w2 = rem >> 5, k = rem & 31;
        const int r0 = w2 + 8 * q, r1 = r0 + 4;
        float2 lo = *reinterpret_cast<const float2*>(&g_Wx[(i0 + r0) * OUTD + h * FH + 2 * k]);
        float2 hi = *reinterpret_cast<const float2*>(&g_Wx[(i0 + r1) * OUTD + h * FH + 2 * k]);
        wi4[q][w2][k] = make_float4(lo.x, lo.y, hi.x, hi.y);
    }
    if (tid < FH / 2)
        av2[tid] = *reinterpret_cast<const u64*>(&a[2 * tid]);
    for (int id = tid; id < JSPAN; id += 128)
        e06s[id] = 0.6f * g_E[(jbase + id) * H + h];

    const int rA = i0 + w, rB = rA + 4, rC = rA + 8, rD = rA + 12;
    const float eiA = 0.6f * g_E[rA * H + h];
    const float eiB = 0.6f * g_E[rB * H + h];
    const float eiC = 0.6f * g_E[rC * H + h];
    const float eiD = 0.6f * g_E[rD * H + h];
    const int* adjA = &adj[rA * N_NODES + jbase];
    const int* adjB = &adj[rB * N_NODES + jbase];
    const int* adjC = &adj[rC * N_NODES + jbase];
    const int* adjD = &adj[rD * N_NODES + jbase];

    float mA = -1e30f, sA = 0.f, mB = -1e30f, sB = 0.f;
    float mC = -1e30f, sC = 0.f, mD = -1e30f, sD = 0.f;
    u64 accA = 0, accB = 0, accC = 0, accD = 0;

    for (int jt = 0; jt < JSPAN; jt += TJ) {
        __syncthreads();
        // ---- stage wxj tile (64 rows x 64 f): 1024 float4, 8/thread ----
        #pragma unroll
        for (int r = 0; r < 8; r++) {
            const int id = tid + r * 128;
            const int jj = id / 16, c4 = id % 16;
            float4 v = *reinterpret_cast<const float4*>(
                &g_Wx[(jbase + jt + jj) * OUTD + h * FH + c4 * 4]);
            *reinterpret_cast<float2*>(&wxj[jj][c4 * 4])     = make_float2(v.x, v.y);
            *reinterpret_cast<float2*>(&wxj[jj][c4 * 4 + 2]) = make_float2(v.z, v.w);
        }
        __syncthreads();

        // ---- e-phase: lane j-cols (jt+lane, jt+32+lane) x 4 rows ----
        const u64* wj0 = reinterpret_cast<const u64*>(&wxj[lane][0]);
        const u64* wj1 = reinterpret_cast<const u64*>(&wxj[lane + 32][0]);
        u64 eA0 = 0, eA1 = 0, eB0 = 0, eB1 = 0;
        u64 eC0 = 0, eC1 = 0, eD0 = 0, eD1 = 0;
        #pragma unroll
        for (int k = 0; k < 32; k++) {
            const u64 avk = av2[k];
            u64 wa, wb, wc, wd;
            lds_v2u64(wa, wb, &wi4[0][w][k]);
            lds_v2u64(wc, wd, &wi4[1][w][k]);
            const u64 j0 = wj0[k];
            const u64 j1 = wj1[k];
            mac_abs2(eA0, avk, wa, j0);  mac_abs2(eA1, avk, wa, j1);
            mac_abs2(eB0, avk, wb, j0);  mac_abs2(eB1, avk, wb, j1);
            mac_abs2(eC0, avk, wc, j0);  mac_abs2(eC1, avk, wc, j1);
            mac_abs2(eD0, avk, wd, j0);  mac_abs2(eD1, avk, wd, j1);
        }
        const float ej0 = e06s[jt + lane], ej1 = e06s[jt + 32 + lane];
        float2 f;
        f = upk2(eA0); float e_A0 = eiA + ej0 + 0.4f * (f.x + f.y);
        f = upk2(eA1); float e_A1 = eiA + ej1 + 0.4f * (f.x + f.y);
        f = upk2(eB0); float e_B0 = eiB + ej0 + 0.4f * (f.x + f.y);
        f = upk2(eB1); float e_B1 = eiB + ej1 + 0.4f * (f.x + f.y);
        f = upk2(eC0); float e_C0 = eiC + ej0 + 0.4f * (f.x + f.y);
        f = upk2(eC1); float e_C1 = eiC + ej1 + 0.4f * (f.x + f.y);
        f = upk2(eD0); float e_D0 = eiD + ej0 + 0.4f * (f.x + f.y);
        f = upk2(eD1); float e_D1 = eiD + ej1 + 0.4f * (f.x + f.y);
        if (adjA[jt + lane]      == 0) e_A0 = -1e30f;
        if (adjA[jt + 32 + lane] == 0) e_A1 = -1e30f;
        if (adjB[jt + lane]      == 0) e_B0 = -1e30f;
        if (adjB[jt + 32 + lane] == 0) e_B1 = -1e30f;
        if (adjC[jt + lane]      == 0) e_C0 = -1e30f;
        if (adjC[jt + 32 + lane] == 0) e_C1 = -1e30f;
        if (adjD[jt + lane]      == 0) e_D0 = -1e30f;
        if (adjD[jt + 32 + lane] == 0) e_D1 = -1e30f;

        // ---- online softmax update, 4 rows ----
        float tA = fmaxf(e_A0, e_A1), tB = fmaxf(e_B0, e_B1);
        float tC = fmaxf(e_C0, e_C1), tD = fmaxf(e_D0, e_D1);
        #pragma unroll
        for (int off = 16; off > 0; off >>= 1) {
            tA = fmaxf(tA, __shfl_xor_sync(0xffffffffu, tA, off));
            tB = fmaxf(tB, __shfl_xor_sync(0xffffffffu, tB, off));
            tC = fmaxf(tC, __shfl_xor_sync(0xffffffffu, tC, off));
            tD = fmaxf(tD, __shfl_xor_sync(0xffffffffu, tD, off));
        }
        const float nA = fmaxf(mA, tA), nB = fmaxf(mB, tB);
        const float nC = fmaxf(mC, tC), nD = fmaxf(mD, tD);
        const float scA = __expf(mA - nA), scB = __expf(mB - nB);
        const float scC = __expf(mC - nC), scD = __expf(mD - nD);
        const float pA0 = __expf(e_A0 - nA), pA1 = __expf(e_A1 - nA);
        const float pB0 = __expf(e_B0 - nB), pB1 = __expf(e_B1 - nB);
        const float pC0 = __expf(e_C0 - nC), pC1 = __expf(e_C1 - nC);
        const float pD0 = __expf(e_D0 - nD), pD1 = __expf(e_D1 - nD);
        sA = sA * scA + pA0 + pA1;  sB = sB * scB + pB0 + pB1;
        sC = sC * scC + pC0 + pC1;  sD = sD * scD + pD0 + pD1;
        mul2(accA, pk2(scA, scA));  mul2(accB, pk2(scB, scB));
        mul2(accC, pk2(scC, scC));  mul2(accD, pk2(scD, scD));
        mA = nA; mB = nB; mC = nC; mD = nD;

        p_ab[w][lane]      = make_float4(pA0, pA0, pB0, pB0);
        p_ab[w][lane + 32] = make_float4(pA1, pA1, pB1, pB1);
        p_cd[w][lane]      = make_float4(pC0, pC0, pD0, pD0);
        p_cd[w][lane + 32] = make_float4(pC1, pC1, pD1, pD1);
        __syncwarp();

        // ---- aggregation: one wv read feeds 4 rows ----
        #pragma unroll
        for (int jj = 0; jj < TJ; jj++) {
            const u64 wv = *reinterpret_cast<const u64*>(&wxj[jj][lane * 2]);
            u64 pa2, pb2, pc2, pd2;
            lds_v2u64(pa2, pb2, &p_ab[w][jj]);
            lds_v2u64(pc2, pd2, &p_cd[w][jj]);
            fma2(accA, pa2, wv);
            fma2(accB, pb2, wv);
            fma2(accC, pc2, wv);
            fma2(accD, pd2, wv);
        }
        __syncwarp();   // agg done before next tile's p overwrite
    }

    // ---- reduce per-lane s partials across the warp ----
    #pragma unroll
    for (int off = 16; off > 0; off >>= 1) {
        sA += __shfl_xor_sync(0xffffffffu, sA, off);
        sB += __shfl_xor_sync(0xffffffffu, sB, off);
        sC += __shfl_xor_sync(0xffffffffu, sC, off);
        sD += __shfl_xor_sync(0xffffffffu, sD, off);
    }

    // ---- write partials (unnormalized) ----
    const int gA = rA * H + h, gB = rB * H + h, gC = rC * H + h, gD = rD * H + h;
    if (lane == 0) {
        g_pm[gA][sp] = mA; g_ps[gA][sp] = sA;
        g_pm[gB][sp] = mB; g_ps[gB][sp] = sB;
        g_pm[gC][sp] = mC; g_ps[gC][sp] = sC;
        g_pm[gD][sp] = mD; g_ps[gD][sp] = sD;
    }
    float2 o;
    o = upk2(accA); *reinterpret_cast<float2*>(&g_pacc[gA][sp][2 * lane]) = o;
    o = upk2(accB); *reinterpret_cast<float2*>(&g_pacc[gB][sp][2 * lane]) = o;
    o = upk2(accC); *reinterpret_cast<float2*>(&g_pacc[gC][sp][2 * lane]) = o;
    o = upk2(accD); *reinterpret_cast<float2*>(&g_pacc[gD][sp][2 * lane]) = o;
}

// ---------------------------------------------------------------------------
// Combine: merge NSPLIT partial softmaxes per (i,h) row. Warp per row.
// ---------------------------------------------------------------------------
__global__ __launch_bounds__(256) void combine_kernel(float* __restrict__ out) {
    const int tid  = threadIdx.x;
    const int w    = tid / 32;
    const int lane = tid % 32;
    const int r    = blockIdx.x * 8 + w;     // 0..3071
    const int i    = r / H;
    const int h    = r % H;

    float mp = (lane < NSPLIT) ? g_pm[r][lane] : -1e30f;
    float ms = mp;
    #pragma unroll
    for (int off = 16; off > 0; off >>= 1)
        ms = fmaxf(ms, __shfl_xor_sync(0xffffffffu, ms, off));
    float fac = (lane < NSPLIT) ? __expf(mp - ms) : 0.f;
    float sv  = (lane < NSPLIT) ? g_ps[r][lane] * fac : 0.f;
    #pragma unroll
    for (int off = 16; off > 0; off >>= 1)
        sv += __shfl_xor_sync(0xffffffffu, sv, off);
    const float f0 = __shfl_sync(0xffffffffu, fac, 0);
    const float f1 = __shfl_sync(0xffffffffu, fac, 1);
    const float f2 = __shfl_sync(0xffffffffu, fac, 2);
    const float f3 = __shfl_sync(0xffffffffu, fac, 3);

    float2 a0 = *reinterpret_cast<const float2*>(&g_pacc[r][0][2 * lane]);
    float2 a1 = *reinterpret_cast<const float2*>(&g_pacc[r][1][2 * lane]);
    float2 a2 = *reinterpret_cast<const float2*>(&g_pacc[r][2][2 * lane]);
    float2 a3 = *reinterpret_cast<const float2*>(&g_pacc[r][3][2 * lane]);
    const float inv = 1.f / sv;
    float ox = (a0.x * f0 + a1.x * f1 + a2.x * f2 + a3.x * f3) * inv;
    float oy = (a0.y * f0 + a1.y * f1 + a2.y * f2 + a3.y * f3) * inv;
    *reinterpret_cast<float2*>(&out[i * OUTD + h * FH + 2 * lane]) = make_float2(ox, oy);
}

// ---------------------------------------------------------------------------
extern "C" void kernel_launch(void* const* d_in, const int* in_sizes, int n_in,
                              void* d_out, int out_size) {
    const float* x = nullptr;
    const int*   adj = nullptr;
    const float* W = nullptr;
    const float* a = nullptr;
    for (int i = 0; i < n_in; i++) {
        switch (in_sizes[i]) {
            case N_NODES * INP:      x   = (const float*)d_in[i]; break;
            case N_NODES * N_NODES:  adj = (const int*)d_in[i];   break;
            case OUTD * INP:         W   = (const float*)d_in[i]; break;
            case FH:                 a   = (const float*)d_in[i]; break;
            default: break;
        }
    }
    float* out = (float*)d_out;

    // >48KB dynamic smem opt-in (host state call; idempotent; not an allocation)
    cudaFuncSetAttribute(gemm_kernel,
                         cudaFuncAttributeMaxDynamicSharedMemorySize, GEMM_SMEM);

    dim3 gg(H, N_NODES / 32);                     // 4 x 24 = 96 blocks
    gemm_kernel<<<gg, 256, GEMM_SMEM>>>(x, W, a);
    dim3 ga((N_NODES / TI) * NSPLIT, H);          // 192 x 4 = 768 blocks
    attn_kernel<<<ga, 128>>>(adj, a);
    combine_kernel<<<N_NODES * H / 8, 256>>>(out);   // 384 blocks
}